// round 4
// baseline (speedup 1.0000x reference)
#include <cuda_runtime.h>
#include <cstdint>

#define Nn    50000
#define Fdim  256
#define Hdim  64
#define NHEAD 4
#define Ee    800000
#define OUTC  16
#define C1    320   // 64 (GCN1) + 256 (GAT1 = 4 heads * 64)
#define C2    32    // 16 (GCN2) + 16 (GAT2)

// ---------------- scratch (static device globals; no allocation allowed) ----
static __device__ int   g_mode;   // 0=int32 1=int64 2=float32 3=float64
static __device__ int   g_flags;  // diagnostic stage flags
static __device__ int   g_src[Ee];
static __device__ int   g_dst[Ee];
static __device__ float g_dinv[Nn];
static __device__ float g_Wcat[Fdim * C1];        // [256][320]
static __device__ float g_Hcat[(size_t)Nn * C1];  // layer-1 pre-agg features
static __device__ float g_Agg [(size_t)Nn * C1];  // layer-1 aggregated -> X2
static __device__ float g_ssrc[Nn * NHEAD];
static __device__ float g_sdst[Nn * NHEAD];
static __device__ float g_m   [Nn * NHEAD];
static __device__ float g_den [Nn * NHEAD];
static __device__ float g_Wcat2[C1 * C2];         // block-diagonal [320][32]
static __device__ float g_H2[(size_t)Nn * C2];    // layer-2 pre-agg
static __device__ float g_s2s[Nn];
static __device__ float g_s2d[Nn];
static __device__ float g_m2[Nn];
static __device__ float g_d2[Nn];

// ---------------- helpers ---------------------------------------------------
__device__ __forceinline__ float leaky(float x) { return x > 0.f ? x : 0.2f * x; }

__device__ __forceinline__ void atomicMaxF(float* a, float v) {
    if (v >= 0.f) atomicMax((int*)a, __float_as_int(v));
    else          atomicMin((unsigned int*)a, __float_as_uint(v));
}

__device__ __forceinline__ int clampN(int v) {
    return v < 0 ? 0 : (v >= Nn ? Nn - 1 : v);
}

// diagnostic: scale = 1.0 when all stages alive; else encodes first dead stage
__device__ __forceinline__ float diag_scale() {
    int f = g_flags;
    if (!(f & 1))  return 0.9f;   // x zero
    if (!(f & 2))  return 0.8f;   // W_gcn1 zero
    if (!(f & 4))  return 0.7f;   // W_gat1 zero
    if (!(f & 8))  return 0.6f;   // Hcat zero (GEMM1 dead)
    if (!(f & 16)) return 0.5f;   // Agg zero (aggregation dead)
    if (!(f & 32)) return 0.4f;   // H2 zero (GEMM2 dead)
    return 1.0f;
}

// ---------------- diagnostics ------------------------------------------------
__global__ void k_flag_reset() { if (threadIdx.x == 0) g_flags = 0; }
__global__ void k_check_ptr(const float* __restrict__ p, int n, int bit) {
    int i = blockIdx.x * blockDim.x + threadIdx.x;
    if (i < n && p[i] != 0.f) atomicOr(&g_flags, 1 << bit);
}
__global__ void k_check_hcat() {
    int i = blockIdx.x * blockDim.x + threadIdx.x;
    if (i < 65536 && g_Hcat[i] != 0.f) atomicOr(&g_flags, 8);
}
__global__ void k_check_agg() {
    int i = blockIdx.x * blockDim.x + threadIdx.x;
    if (i < 65536 && g_Agg[i] != 0.f) atomicOr(&g_flags, 16);
}
__global__ void k_check_h2() {
    int i = blockIdx.x * blockDim.x + threadIdx.x;
    if (i < 65536 && g_H2[i] != 0.f) atomicOr(&g_flags, 32);
}

// ---------------- edge dtype detect + convert -------------------------------
__global__ void k_detect(const void* edges) {
    const unsigned int* p = (const unsigned int*)edges;
    __shared__ int en, on, big;
    if (threadIdx.x == 0) { en = 0; on = 0; big = 0; }
    __syncthreads();
    for (int i = threadIdx.x; i < 1024; i += blockDim.x) {
        unsigned int a = p[2 * i];
        unsigned int b = p[2 * i + 1];
        if (a != 0) en = 1;                               // benign race
        if (b != 0) on = 1;
        if (a >= (1u << 20) || b >= (1u << 20)) big = 1;
    }
    __syncthreads();
    if (threadIdx.x == 0) {
        int mode;
        if (on == 0 && en != 0)      mode = 1;  // int64
        else if (en == 0 && on != 0) mode = 3;  // float64
        else if (big)                mode = 2;  // float32
        else                         mode = 0;  // int32
        g_mode = mode;
    }
}

__global__ void k_convert(const void* edges) {
    int e = blockIdx.x * blockDim.x + threadIdx.x;
    if (e >= Ee) return;
    int s, d;
    int mode = g_mode;
    if (mode == 0) {
        const int* q = (const int*)edges;
        s = q[e]; d = q[Ee + e];
    } else if (mode == 1) {
        const int* q = (const int*)edges;       // low words of int64
        s = q[2 * e]; d = q[2 * (Ee + e)];
    } else if (mode == 2) {
        const float* q = (const float*)edges;
        s = (int)q[e]; d = (int)q[Ee + e];
    } else {
        const double* q = (const double*)edges;
        s = (int)q[e]; d = (int)q[Ee + e];
    }
    g_src[e] = clampN(s);
    g_dst[e] = clampN(d);
}

// ---------------- degree / symmetric norm -----------------------------------
__global__ void k_deg_init() {
    int i = blockIdx.x * blockDim.x + threadIdx.x;
    if (i < Nn) g_dinv[i] = 1.0f;           // self loop
}
__global__ void k_deg_edges() {
    int e = blockIdx.x * blockDim.x + threadIdx.x;
    if (e < Ee) atomicAdd(&g_dinv[g_dst[e]], 1.0f);
}
__global__ void k_deg_fin() {
    int i = blockIdx.x * blockDim.x + threadIdx.x;
    if (i < Nn) g_dinv[i] = rsqrtf(g_dinv[i]);
}

// ---------------- weight packing --------------------------------------------
__global__ void k_build_w1(const float* __restrict__ Wg, const float* __restrict__ Wa) {
    int idx = blockIdx.x * blockDim.x + threadIdx.x;
    if (idx >= Fdim * C1) return;
    int r = idx / C1, c = idx % C1;
    g_Wcat[idx] = (c < Hdim) ? Wg[r * Hdim + c] : Wa[r * 256 + (c - Hdim)];
}
__global__ void k_build_w2(const float* __restrict__ Wg2, const float* __restrict__ Wa2) {
    int idx = blockIdx.x * blockDim.x + threadIdx.x;
    if (idx >= C1 * C2) return;
    int r = idx / C2, c = idx % C2;
    float v = 0.f;
    if (r < Hdim && c < OUTC)          v = Wg2[r * OUTC + c];
    else if (r >= Hdim && c >= OUTC)   v = Wa2[(r - Hdim) * OUTC + (c - OUTC)];
    g_Wcat2[idx] = v;
}

// ---------------- SGEMM (register-blocked, fp32) ----------------------------
template<int BM, int BN, int BK, int TM, int TN>
__global__ void __launch_bounds__(256)
k_sgemm(const float* __restrict__ A, const float* __restrict__ B,
        float* __restrict__ C, int M, int N, int K)
{
    constexpr int NT = (BM / TM) * (BN / TN);   // must be 256
    __shared__ float As[BK][BM];
    __shared__ float Bs[BK][BN];
    const int tid = threadIdx.x;
    const int rowBase = blockIdx.y * BM;
    const int colBase = blockIdx.x * BN;
    const int trow = tid / (BN / TN);
    const int tcol = tid % (BN / TN);

    float acc[TM][TN];
#pragma unroll
    for (int i = 0; i < TM; i++)
#pragma unroll
        for (int j = 0; j < TN; j++) acc[i][j] = 0.f;

    for (int k0 = 0; k0 < K; k0 += BK) {
        for (int i = tid; i < BM * BK; i += NT) {
            int m = i / BK, k = i % BK;
            int gr = rowBase + m;
            As[k][m] = (gr < M) ? A[(size_t)gr * K + k0 + k] : 0.f;
        }
        for (int i = tid; i < BK * BN; i += NT) {
            int k = i / BN, n = i % BN;
            Bs[k][n] = B[(size_t)(k0 + k) * N + colBase + n];
        }
        __syncthreads();
#pragma unroll
        for (int k = 0; k < BK; k++) {
            float ra[TM], rb[TN];
#pragma unroll
            for (int i = 0; i < TM; i++) ra[i] = As[k][trow * TM + i];
#pragma unroll
            for (int j = 0; j < TN; j++) rb[j] = Bs[k][tcol * TN + j];
#pragma unroll
            for (int i = 0; i < TM; i++)
#pragma unroll
                for (int j = 0; j < TN; j++) acc[i][j] += ra[i] * rb[j];
        }
        __syncthreads();
    }
#pragma unroll
    for (int i = 0; i < TM; i++) {
        int gr = rowBase + trow * TM + i;
        if (gr >= M) continue;
#pragma unroll
        for (int j = 0; j < TN; j++)
            C[(size_t)gr * N + colBase + tcol * TN + j] = acc[i][j];
    }
}

// ---------------- GAT1 attention scores -------------------------------------
__global__ void k_scores1(const float* __restrict__ a_s, const float* __restrict__ a_d) {
    int idx = blockIdx.x * blockDim.x + threadIdx.x;
    if (idx >= Nn * NHEAD) return;
    int n = idx / NHEAD, h = idx % NHEAD;
    const float* row = g_Hcat + (size_t)n * C1 + Hdim + h * Hdim;
    float s1 = 0.f, s2 = 0.f;
#pragma unroll 8
    for (int c = 0; c < Hdim; c++) {
        float v = row[c];
        s1 += v * a_s[h * Hdim + c];
        s2 += v * a_d[h * Hdim + c];
    }
    g_ssrc[idx] = s1;
    g_sdst[idx] = s2;
}

// ---------------- GAT1 softmax (max / denom) --------------------------------
__global__ void k_m1_init() {
    int idx = blockIdx.x * blockDim.x + threadIdx.x;
    if (idx >= Nn * NHEAD) return;
    g_m[idx] = leaky(g_ssrc[idx] + g_sdst[idx]);   // self loop
}
__global__ void k_m1_edges() {
    int t = blockIdx.x * blockDim.x + threadIdx.x;
    if (t >= Ee * NHEAD) return;
    int e = t >> 2, h = t & 3;
    int u = g_src[e], v = g_dst[e];
    float val = leaky(g_ssrc[u * NHEAD + h] + g_sdst[v * NHEAD + h]);
    atomicMaxF(&g_m[v * NHEAD + h], val);
}
__global__ void k_d1_init() {
    int idx = blockIdx.x * blockDim.x + threadIdx.x;
    if (idx >= Nn * NHEAD) return;
    float e = leaky(g_ssrc[idx] + g_sdst[idx]);
    g_den[idx] = expf(e - g_m[idx]);
}
__global__ void k_d1_edges() {
    int t = blockIdx.x * blockDim.x + threadIdx.x;
    if (t >= Ee * NHEAD) return;
    int e = t >> 2, h = t & 3;
    int u = g_src[e], v = g_dst[e];
    int p = v * NHEAD + h;
    float val = leaky(g_ssrc[u * NHEAD + h] + g_sdst[p]);
    atomicAdd(&g_den[p], expf(val - g_m[p]));
}

// ---------------- layer-1 aggregation (GCN cols 0-63, GAT cols 64-319) ------
__global__ void k_agg1_init() {
    int idx = blockIdx.x * blockDim.x + threadIdx.x;
    if (idx >= Nn * C1) return;
    int n = idx / C1, c = idx % C1;
    float scale;
    if (c < Hdim) {
        float d = g_dinv[n];
        scale = d * d;
    } else {
        int p = n * NHEAD + ((c - Hdim) >> 6);
        float e = leaky(g_ssrc[p] + g_sdst[p]);
        scale = expf(e - g_m[p]) / g_den[p];
    }
    g_Agg[idx] = scale * g_Hcat[idx];
}

__global__ void __launch_bounds__(256) k_agg1_edges() {
    int w    = (blockIdx.x * blockDim.x + threadIdx.x) >> 5;
    int lane = threadIdx.x & 31;
    if (w >= Ee) return;
    int u = g_src[w], v = g_dst[w];
    float wg = g_dinv[u] * g_dinv[v];
    float alpha[NHEAD];
#pragma unroll
    for (int h = 0; h < NHEAD; h++) {
        int p = v * NHEAD + h;
        float e = leaky(g_ssrc[u * NHEAD + h] + g_sdst[p]);
        alpha[h] = expf(e - g_m[p]) / g_den[p];
    }
    const float* hrow = g_Hcat + (size_t)u * C1;
    float*       arow = g_Agg  + (size_t)v * C1;
#pragma unroll
    for (int i = 0; i < C1 / 32; i++) {
        int c = lane + 32 * i;
        float s = (c < Hdim) ? wg : alpha[(c - Hdim) >> 6];
        atomicAdd(&arow[c], s * hrow[c]);
    }
}

__global__ void k_relu_bias(const float* __restrict__ bg, const float* __restrict__ ba) {
    int idx = blockIdx.x * blockDim.x + threadIdx.x;
    if (idx >= Nn * C1) return;
    int c = idx % C1;
    float b = (c < Hdim) ? bg[c] : ba[c - Hdim];
    g_Agg[idx] = fmaxf(g_Agg[idx] + b, 0.f);
}

// ---------------- GAT2 scores / softmax -------------------------------------
__global__ void k_scores2(const float* __restrict__ a_s, const float* __restrict__ a_d) {
    int n = blockIdx.x * blockDim.x + threadIdx.x;
    if (n >= Nn) return;
    const float* row = g_H2 + (size_t)n * C2 + OUTC;
    float s1 = 0.f, s2 = 0.f;
#pragma unroll
    for (int c = 0; c < OUTC; c++) {
        float v = row[c];
        s1 += v * a_s[c];
        s2 += v * a_d[c];
    }
    g_s2s[n] = s1;
    g_s2d[n] = s2;
}
__global__ void k_m2_init() {
    int n = blockIdx.x * blockDim.x + threadIdx.x;
    if (n < Nn) g_m2[n] = leaky(g_s2s[n] + g_s2d[n]);
}
__global__ void k_m2_edges() {
    int e = blockIdx.x * blockDim.x + threadIdx.x;
    if (e >= Ee) return;
    int u = g_src[e], v = g_dst[e];
    atomicMaxF(&g_m2[v], leaky(g_s2s[u] + g_s2d[v]));
}
__global__ void k_d2_init() {
    int n = blockIdx.x * blockDim.x + threadIdx.x;
    if (n >= Nn) return;
    g_d2[n] = expf(leaky(g_s2s[n] + g_s2d[n]) - g_m2[n]);
}
__global__ void k_d2_edges() {
    int e = blockIdx.x * blockDim.x + threadIdx.x;
    if (e >= Ee) return;
    int u = g_src[e], v = g_dst[e];
    atomicAdd(&g_d2[v], expf(leaky(g_s2s[u] + g_s2d[v]) - g_m2[v]));
}

// ---------------- layer-2 aggregation straight into d_out -------------------
__global__ void k_out_init(float* __restrict__ out,
                           const float* __restrict__ bg2, const float* __restrict__ ba2) {
    int idx = blockIdx.x * blockDim.x + threadIdx.x;
    if (idx >= Nn * C2) return;
    int n = idx / C2, c = idx % C2;
    float v;
    if (c < OUTC) {
        float d = g_dinv[n];
        v = bg2[c] + d * d * g_H2[idx];
    } else {
        float al = expf(leaky(g_s2s[n] + g_s2d[n]) - g_m2[n]) / g_d2[n];
        v = ba2[c - OUTC] + al * g_H2[idx];
    }
    out[idx] = diag_scale() * v;
}

__global__ void __launch_bounds__(256) k_out_edges(float* __restrict__ out) {
    int w    = (blockIdx.x * blockDim.x + threadIdx.x) >> 5;
    int lane = threadIdx.x & 31;
    if (w >= Ee) return;
    int u = g_src[w], v = g_dst[w];
    float s;
    if (lane < OUTC) {
        s = g_dinv[u] * g_dinv[v];
    } else {
        s = expf(leaky(g_s2s[u] + g_s2d[v]) - g_m2[v]) / g_d2[v];
    }
    atomicAdd(&out[(size_t)v * C2 + lane], diag_scale() * s * g_H2[(size_t)u * C2 + lane]);
}

// ---------------- launch ----------------------------------------------------
static inline int cdiv(int a, int b) { return (a + b - 1) / b; }

extern "C" void kernel_launch(void* const* d_in, const int* in_sizes, int n_in,
                              void* d_out, int out_size)
{
    // Logical inputs identified by element count (rebind if order differs).
    static const long long EXP[14] = {12800000LL, 1600000LL, 16384LL, 64LL, 1024LL,
                                      16LL, 65536LL, 256LL, 256LL, 256LL,
                                      4096LL, 16LL, 16LL, 16LL};
    const void* slot[14];
    for (int i = 0; i < 14; i++) slot[i] = (n_in > i) ? d_in[i] : d_in[0];

    if (n_in >= 14) {
        bool id = true;
        for (int i = 0; i < 14; i++) {
            long long s = in_sizes[i];
            if (i == 1) { if (s != 1600000LL && s != 3200000LL) id = false; }
            else if (s != EXP[i]) id = false;
        }
        if (!id) {
            bool used[64];
            for (int i = 0; i < 64; i++) used[i] = false;
            bool ok = true;
            const void* tmp[14];
            for (int j = 0; j < 14 && ok; j++) {
                int found = -1;
                for (int i = 0; i < n_in && i < 64; i++) {
                    if (used[i]) continue;
                    long long s = in_sizes[i];
                    bool m = (j == 1) ? (s == 1600000LL || s == 3200000LL)
                                      : (s == EXP[j]);
                    if (m) { found = i; break; }
                }
                if (found < 0) ok = false;
                else { used[found] = true; tmp[j] = d_in[found]; }
            }
            if (ok) for (int j = 0; j < 14; j++) slot[j] = tmp[j];
        }
    }

    const float* x      = (const float*)slot[0];
    const void*  edges  = slot[1];
    const float* W_g1   = (const float*)slot[2];
    const float* b_g1   = (const float*)slot[3];
    const float* W_g2   = (const float*)slot[4];
    const float* b_g2   = (const float*)slot[5];
    const float* W_a1   = (const float*)slot[6];
    const float* as1    = (const float*)slot[7];
    const float* ad1    = (const float*)slot[8];
    const float* b_a1   = (const float*)slot[9];
    const float* W_a2   = (const float*)slot[10];
    const float* as2    = (const float*)slot[11];
    const float* ad2    = (const float*)slot[12];
    const float* b_a2   = (const float*)slot[13];
    float* out = (float*)d_out;
    (void)out_size;

    // CRITICAL: resolve device addresses of __device__ globals for use as
    // kernel arguments. Referencing the symbols directly from host code
    // yields the host shadow address (silently wrong on ATS-capable GB300).
    void *p_Wcat = nullptr, *p_Hcat = nullptr, *p_Agg = nullptr,
         *p_Wcat2 = nullptr, *p_H2 = nullptr;
    cudaGetSymbolAddress(&p_Wcat,  g_Wcat);
    cudaGetSymbolAddress(&p_Hcat,  g_Hcat);
    cudaGetSymbolAddress(&p_Agg,   g_Agg);
    cudaGetSymbolAddress(&p_Wcat2, g_Wcat2);
    cudaGetSymbolAddress(&p_H2,    g_H2);

    const int T = 256;

    // diagnostics: reset + input liveness
    k_flag_reset<<<1, 32>>>();
    k_check_ptr<<<cdiv(65536, T), T>>>(x,    65536, 0);
    k_check_ptr<<<cdiv(16384, T), T>>>(W_g1, 16384, 1);
    k_check_ptr<<<cdiv(65536, T), T>>>(W_a1, 65536, 2);

    // edge dtype detect + convert
    k_detect<<<1, T>>>(edges);
    k_convert<<<cdiv(Ee, T), T>>>(edges);

    // degree / norm
    k_deg_init <<<cdiv(Nn, T), T>>>();
    k_deg_edges<<<cdiv(Ee, T), T>>>();
    k_deg_fin  <<<cdiv(Nn, T), T>>>();

    // packed weights
    k_build_w1<<<cdiv(Fdim * C1, T), T>>>(W_g1, W_a1);
    k_build_w2<<<cdiv(C1 * C2, T), T>>>(W_g2, W_a2);

    // GEMM1: Hcat = x @ Wcat   (50000 x 256 @ 256 x 320)
    {
        dim3 grid(C1 / 64, cdiv(Nn, 128));
        k_sgemm<128, 64, 16, 8, 4><<<grid, 256>>>(
            x, (const float*)p_Wcat, (float*)p_Hcat, Nn, C1, Fdim);
    }
    k_check_hcat<<<cdiv(65536, T), T>>>();

    // GAT1 softmax pipeline
    k_scores1<<<cdiv(Nn * NHEAD, T), T>>>(as1, ad1);
    k_m1_init <<<cdiv(Nn * NHEAD, T), T>>>();
    k_m1_edges<<<cdiv(Ee * NHEAD, T), T>>>();
    k_d1_init <<<cdiv(Nn * NHEAD, T), T>>>();
    k_d1_edges<<<cdiv(Ee * NHEAD, T), T>>>();

    // layer-1 aggregation + relu/bias
    k_agg1_init <<<cdiv(Nn * C1, T), T>>>();
    k_agg1_edges<<<cdiv(Ee * 32, T), T>>>();
    k_relu_bias <<<cdiv(Nn * C1, T), T>>>(b_g1, b_a1);
    k_check_agg<<<cdiv(65536, T), T>>>();

    // GEMM2: H2 = X2 @ Wcat2   (50000 x 320 @ 320 x 32)
    {
        dim3 grid(C2 / 32, cdiv(Nn, 128));
        k_sgemm<128, 32, 16, 8, 2><<<grid, 256>>>(
            (const float*)p_Agg, (const float*)p_Wcat2, (float*)p_H2, Nn, C2, C1);
    }
    k_check_h2<<<cdiv(65536, T), T>>>();

    // GAT2 softmax pipeline
    k_scores2<<<cdiv(Nn, T), T>>>(as2, ad2);
    k_m2_init <<<cdiv(Nn, T), T>>>();
    k_m2_edges<<<cdiv(Ee, T), T>>>();
    k_d2_init <<<cdiv(Nn, T), T>>>();
    k_d2_edges<<<cdiv(Ee, T), T>>>();

    // layer-2 aggregation into d_out
    k_out_init <<<cdiv(Nn * C2, T), T>>>(out, b_g2, b_a2);
    k_out_edges<<<cdiv(Ee * 32, T), T>>>(out);
}

// round 6
// speedup vs baseline: 1.6599x; 1.6599x over previous
#include <cuda_runtime.h>
#include <cstdint>

#define Nn    50000
#define Fdim  256
#define Hdim  64
#define NHEAD 4
#define Ee    800000
#define OUTC  16
#define C1    320   // 64 (GCN1) + 256 (GAT1 = 4 heads * 64)
#define C2    32    // 16 (GCN2) + 16 (GAT2)

// ---------------- scratch (static device globals; no allocation allowed) ----
static __device__ int   g_mode;   // 0=int32 1=int64 2=float32 3=float64
static __device__ __align__(16) int   g_src[Ee];
static __device__ __align__(16) int   g_dst[Ee];
static __device__ __align__(16) float g_dinv[Nn];
static __device__ __align__(16) float g_Wcat[Fdim * C1];        // [256][320]
static __device__ __align__(16) float g_Hcat[(size_t)Nn * C1];
static __device__ __align__(16) float g_Agg [(size_t)Nn * C1];
static __device__ __align__(16) float g_ssrc[Nn * NHEAD];
static __device__ __align__(16) float g_sdst[Nn * NHEAD];
static __device__ __align__(16) float g_m   [Nn * NHEAD];
static __device__ __align__(16) float g_den [Nn * NHEAD];
static __device__ __align__(16) float g_Wcat2[C1 * C2];         // block-diag [320][32]
static __device__ __align__(16) float g_H2[(size_t)Nn * C2];
static __device__ __align__(16) float g_s2s[Nn];
static __device__ __align__(16) float g_s2d[Nn];
static __device__ __align__(16) float g_m2[Nn];
static __device__ __align__(16) float g_d2[Nn];

// ---------------- helpers ---------------------------------------------------
__device__ __forceinline__ float leaky(float x) { return x > 0.f ? x : 0.2f * x; }

__device__ __forceinline__ void atomicMaxF(float* a, float v) {
    if (v >= 0.f) atomicMax((int*)a, __float_as_int(v));
    else          atomicMin((unsigned int*)a, __float_as_uint(v));
}

__device__ __forceinline__ int clampN(int v) {
    return v < 0 ? 0 : (v >= Nn ? Nn - 1 : v);
}

// vector reduction: 1 instruction, 16B L2 RMW (sm_90+)
__device__ __forceinline__ void red4(float* p, float4 v) {
    asm volatile("red.global.add.v4.f32 [%0], {%1,%2,%3,%4};"
                 :: "l"(p), "f"(v.x), "f"(v.y), "f"(v.z), "f"(v.w) : "memory");
}

// ---------------- edge dtype detect + convert -------------------------------
__global__ void k_detect(const void* edges) {
    const unsigned int* p = (const unsigned int*)edges;
    __shared__ int en, on, big;
    if (threadIdx.x == 0) { en = 0; on = 0; big = 0; }
    __syncthreads();
    for (int i = threadIdx.x; i < 1024; i += blockDim.x) {
        unsigned int a = p[2 * i];
        unsigned int b = p[2 * i + 1];
        if (a != 0) en = 1;
        if (b != 0) on = 1;
        if (a >= (1u << 20) || b >= (1u << 20)) big = 1;
    }
    __syncthreads();
    if (threadIdx.x == 0) {
        int mode;
        if (on == 0 && en != 0)      mode = 1;  // int64
        else if (en == 0 && on != 0) mode = 3;  // float64
        else if (big)                mode = 2;  // float32
        else                         mode = 0;  // int32
        g_mode = mode;
    }
}

__global__ void k_convert(const void* edges) {
    int e = blockIdx.x * blockDim.x + threadIdx.x;
    if (e >= Ee) return;
    int s, d;
    int mode = g_mode;
    if (mode == 0) {
        const int* q = (const int*)edges;
        s = q[e]; d = q[Ee + e];
    } else if (mode == 1) {
        const int* q = (const int*)edges;
        s = q[2 * e]; d = q[2 * (Ee + e)];
    } else if (mode == 2) {
        const float* q = (const float*)edges;
        s = (int)q[e]; d = (int)q[Ee + e];
    } else {
        const double* q = (const double*)edges;
        s = (int)q[e]; d = (int)q[Ee + e];
    }
    g_src[e] = clampN(s);
    g_dst[e] = clampN(d);
}

// ---------------- degree / symmetric norm -----------------------------------
__global__ void k_deg_init() {
    int i = blockIdx.x * blockDim.x + threadIdx.x;
    if (i < Nn) g_dinv[i] = 1.0f;           // self loop
}
__global__ void k_deg_edges() {
    int e = blockIdx.x * blockDim.x + threadIdx.x;
    if (e < Ee) atomicAdd(&g_dinv[g_dst[e]], 1.0f);
}
__global__ void k_deg_fin() {
    int i = blockIdx.x * blockDim.x + threadIdx.x;
    if (i < Nn) g_dinv[i] = rsqrtf(g_dinv[i]);
}

// ---------------- weight packing --------------------------------------------
__global__ void k_build_w1(const float* __restrict__ Wg, const float* __restrict__ Wa) {
    int idx = blockIdx.x * blockDim.x + threadIdx.x;
    if (idx >= Fdim * C1) return;
    int r = idx / C1, c = idx % C1;
    g_Wcat[idx] = (c < Hdim) ? Wg[r * Hdim + c] : Wa[r * 256 + (c - Hdim)];
}
__global__ void k_build_w2(const float* __restrict__ Wg2, const float* __restrict__ Wa2) {
    int idx = blockIdx.x * blockDim.x + threadIdx.x;
    if (idx >= C1 * C2) return;
    int r = idx / C2, c = idx % C2;
    float v = 0.f;
    if (r < Hdim && c < OUTC)          v = Wg2[r * OUTC + c];
    else if (r >= Hdim && c >= OUTC)   v = Wa2[(r - Hdim) * OUTC + (c - OUTC)];
    g_Wcat2[idx] = v;
}

// ---------------- SGEMM, float4-vectorized ----------------------------------
template<int BM, int BN, int BK, int TM, int TN>
__global__ void __launch_bounds__((BM / TM) * (BN / TN))
k_sgemm4(const float* __restrict__ A, const float* __restrict__ B,
         float* __restrict__ C, int M, int N, int K)
{
    constexpr int NT = (BM / TM) * (BN / TN);
    __shared__ float As[BK][BM];
    __shared__ float Bs[BK][BN];
    const int tid = threadIdx.x;
    const int rowBase = blockIdx.y * BM;
    const int colBase = blockIdx.x * BN;
    const int trow = tid / (BN / TN);
    const int tcol = tid % (BN / TN);

    float acc[TM][TN];
#pragma unroll
    for (int i = 0; i < TM; i++)
#pragma unroll
        for (int j = 0; j < TN; j++) acc[i][j] = 0.f;

    for (int k0 = 0; k0 < K; k0 += BK) {
        constexpr int AF = BM * BK / 4;     // float4 loads for A tile
#pragma unroll
        for (int f = tid; f < AF; f += NT) {
            int m  = f % BM;
            int kk = (f / BM) * 4;
            int gr = rowBase + m;
            float4 v = make_float4(0.f, 0.f, 0.f, 0.f);
            if (gr < M) v = *(const float4*)&A[(size_t)gr * K + k0 + kk];
            As[kk + 0][m] = v.x;
            As[kk + 1][m] = v.y;
            As[kk + 2][m] = v.z;
            As[kk + 3][m] = v.w;
        }
        constexpr int BF = BK * BN / 4;     // float4 loads for B tile
#pragma unroll
        for (int f = tid; f < BF; f += NT) {
            int k  = f / (BN / 4);
            int nn = (f % (BN / 4)) * 4;
            *(float4*)&Bs[k][nn] = *(const float4*)&B[(size_t)(k0 + k) * N + colBase + nn];
        }
        __syncthreads();
#pragma unroll
        for (int k = 0; k < BK; k++) {
            float ra[TM], rb[TN];
#pragma unroll
            for (int i = 0; i < TM; i += 4)
                *(float4*)&ra[i] = *(const float4*)&As[k][trow * TM + i];
#pragma unroll
            for (int j = 0; j < TN; j += 4)
                *(float4*)&rb[j] = *(const float4*)&Bs[k][tcol * TN + j];
#pragma unroll
            for (int i = 0; i < TM; i++)
#pragma unroll
                for (int j = 0; j < TN; j++) acc[i][j] += ra[i] * rb[j];
        }
        __syncthreads();
    }
#pragma unroll
    for (int i = 0; i < TM; i++) {
        int gr = rowBase + trow * TM + i;
        if (gr >= M) continue;
#pragma unroll
        for (int j = 0; j < TN; j += 4)
            *(float4*)&C[(size_t)gr * N + colBase + tcol * TN + j] = *(float4*)&acc[i][j];
    }
}

// ---------------- GAT1 scores (+ fused m init) -------------------------------
__global__ void k_scores1(const float* __restrict__ a_s, const float* __restrict__ a_d) {
    int idx = blockIdx.x * blockDim.x + threadIdx.x;
    if (idx >= Nn * NHEAD) return;
    int n = idx / NHEAD, h = idx % NHEAD;
    const float* row = g_Hcat + (size_t)n * C1 + Hdim + h * Hdim;
    float s1 = 0.f, s2 = 0.f;
#pragma unroll 8
    for (int c = 0; c < Hdim; c++) {
        float v = row[c];
        s1 += v * a_s[h * Hdim + c];
        s2 += v * a_d[h * Hdim + c];
    }
    g_ssrc[idx] = s1;
    g_sdst[idx] = s2;
    g_m[idx]    = leaky(s1 + s2);   // self-loop init for segment max
}

// ---------------- GAT1 softmax (max / denom), edge passes --------------------
__global__ void k_m1_edges() {
    int e = blockIdx.x * blockDim.x + threadIdx.x;
    if (e >= Ee) return;
    int u = g_src[e], v = g_dst[e];
    float4 su = *(const float4*)&g_ssrc[u * 4];
    float4 sv = *(const float4*)&g_sdst[v * 4];
    atomicMaxF(&g_m[v * 4 + 0], leaky(su.x + sv.x));
    atomicMaxF(&g_m[v * 4 + 1], leaky(su.y + sv.y));
    atomicMaxF(&g_m[v * 4 + 2], leaky(su.z + sv.z));
    atomicMaxF(&g_m[v * 4 + 3], leaky(su.w + sv.w));
}
__global__ void k_d1_init() {
    int idx = blockIdx.x * blockDim.x + threadIdx.x;
    if (idx >= Nn * NHEAD) return;
    float e = leaky(g_ssrc[idx] + g_sdst[idx]);
    g_den[idx] = expf(e - g_m[idx]);
}
__global__ void k_d1_edges() {
    int e = blockIdx.x * blockDim.x + threadIdx.x;
    if (e >= Ee) return;
    int u = g_src[e], v = g_dst[e];
    float4 su = *(const float4*)&g_ssrc[u * 4];
    float4 sv = *(const float4*)&g_sdst[v * 4];
    float4 mm = *(const float4*)&g_m[v * 4];
    float4 p;
    p.x = expf(leaky(su.x + sv.x) - mm.x);
    p.y = expf(leaky(su.y + sv.y) - mm.y);
    p.z = expf(leaky(su.z + sv.z) - mm.z);
    p.w = expf(leaky(su.w + sv.w) - mm.w);
    red4(&g_den[v * 4], p);
}

// ---------------- layer-1 aggregation ----------------------------------------
__global__ void k_agg1_init() {
    int idx = blockIdx.x * blockDim.x + threadIdx.x;
    if (idx >= Nn * (C1 / 4)) return;
    int n = idx / (C1 / 4), i = idx % (C1 / 4);
    int cc = i * 4;
    float scale;
    if (cc < Hdim) {
        float d = g_dinv[n];
        scale = d * d;
    } else {
        int p = n * NHEAD + ((cc - Hdim) >> 6);
        float e = leaky(g_ssrc[p] + g_sdst[p]);
        scale = expf(e - g_m[p]) / g_den[p];
    }
    float4 h = *(const float4*)&g_Hcat[(size_t)n * C1 + cc];
    h.x *= scale; h.y *= scale; h.z *= scale; h.w *= scale;
    *(float4*)&g_Agg[(size_t)n * C1 + cc] = h;
}

__global__ void __launch_bounds__(256) k_agg1_edges() {
    int w    = (blockIdx.x * blockDim.x + threadIdx.x) >> 5;
    int lane = threadIdx.x & 31;
    if (w >= Ee) return;
    int u = g_src[w], v = g_dst[w];
    float wg = g_dinv[u] * g_dinv[v];
    float alpha[NHEAD];
#pragma unroll
    for (int h = 0; h < NHEAD; h++) {
        int p = v * NHEAD + h;
        float e = leaky(g_ssrc[u * NHEAD + h] + g_sdst[p]);
        alpha[h] = expf(e - g_m[p]) / g_den[p];
    }
    const float* hrow = g_Hcat + (size_t)u * C1;
    float*       arow = g_Agg  + (size_t)v * C1;
    // 80 float4 chunks; chunk boundaries never cross the 64-col regions
#pragma unroll
    for (int i = lane; i < C1 / 4; i += 32) {
        int cc = i * 4;
        float s = (cc < Hdim) ? wg : alpha[(cc - Hdim) >> 6];
        float4 h = *(const float4*)&hrow[cc];
        h.x *= s; h.y *= s; h.z *= s; h.w *= s;
        red4(&arow[cc], h);
    }
}

__global__ void k_relu_bias(const float* __restrict__ bg, const float* __restrict__ ba) {
    int idx = blockIdx.x * blockDim.x + threadIdx.x;
    if (idx >= Nn * (C1 / 4)) return;
    int n = idx / (C1 / 4), i = idx % (C1 / 4);
    int cc = i * 4;
    float4 a = *(float4*)&g_Agg[(size_t)n * C1 + cc];
    float b0, b1, b2, b3;
    if (cc < Hdim) { b0 = bg[cc]; b1 = bg[cc+1]; b2 = bg[cc+2]; b3 = bg[cc+3]; }
    else { int c = cc - Hdim; b0 = ba[c]; b1 = ba[c+1]; b2 = ba[c+2]; b3 = ba[c+3]; }
    a.x = fmaxf(a.x + b0, 0.f);
    a.y = fmaxf(a.y + b1, 0.f);
    a.z = fmaxf(a.z + b2, 0.f);
    a.w = fmaxf(a.w + b3, 0.f);
    *(float4*)&g_Agg[(size_t)n * C1 + cc] = a;
}

// ---------------- GAT2 scores / softmax --------------------------------------
__global__ void k_scores2(const float* __restrict__ a_s, const float* __restrict__ a_d) {
    int n = blockIdx.x * blockDim.x + threadIdx.x;
    if (n >= Nn) return;
    const float* row = g_H2 + (size_t)n * C2 + OUTC;
    float s1 = 0.f, s2 = 0.f;
#pragma unroll
    for (int c = 0; c < OUTC; c++) {
        float v = row[c];
        s1 += v * a_s[c];
        s2 += v * a_d[c];
    }
    g_s2s[n] = s1;
    g_s2d[n] = s2;
    g_m2[n]  = leaky(s1 + s2);
}
__global__ void k_m2_edges() {
    int e = blockIdx.x * blockDim.x + threadIdx.x;
    if (e >= Ee) return;
    int u = g_src[e], v = g_dst[e];
    atomicMaxF(&g_m2[v], leaky(g_s2s[u] + g_s2d[v]));
}
__global__ void k_d2_init() {
    int n = blockIdx.x * blockDim.x + threadIdx.x;
    if (n >= Nn) return;
    g_d2[n] = expf(leaky(g_s2s[n] + g_s2d[n]) - g_m2[n]);
}
__global__ void k_d2_edges() {
    int e = blockIdx.x * blockDim.x + threadIdx.x;
    if (e >= Ee) return;
    int u = g_src[e], v = g_dst[e];
    atomicAdd(&g_d2[v], expf(leaky(g_s2s[u] + g_s2d[v]) - g_m2[v]));
}

// ---------------- layer-2 aggregation into d_out ------------------------------
__global__ void k_out_init(float* __restrict__ out,
                           const float* __restrict__ bg2, const float* __restrict__ ba2) {
    int idx = blockIdx.x * blockDim.x + threadIdx.x;
    if (idx >= Nn * C2) return;
    int n = idx / C2, c = idx % C2;
    float v;
    if (c < OUTC) {
        float d = g_dinv[n];
        v = bg2[c] + d * d * g_H2[idx];
    } else {
        float al = expf(leaky(g_s2s[n] + g_s2d[n]) - g_m2[n]) / g_d2[n];
        v = ba2[c - OUTC] + al * g_H2[idx];
    }
    out[idx] = v;
}

// 8 lanes per edge, one v4 red each
__global__ void __launch_bounds__(256) k_out_edges(float* __restrict__ out) {
    int t = blockIdx.x * blockDim.x + threadIdx.x;
    int e = t >> 3, j = t & 7;
    if (e >= Ee) return;
    int u = g_src[e], v = g_dst[e];
    float s;
    if (j < 4) {
        s = g_dinv[u] * g_dinv[v];
    } else {
        s = expf(leaky(g_s2s[u] + g_s2d[v]) - g_m2[v]) / g_d2[v];
    }
    float4 h = *(const float4*)&g_H2[(size_t)u * C2 + j * 4];
    h.x *= s; h.y *= s; h.z *= s; h.w *= s;
    red4(&out[(size_t)v * C2 + j * 4], h);
}

// ---------------- launch -----------------------------------------------------
static inline int cdiv(int a, int b) { return (a + b - 1) / b; }

extern "C" void kernel_launch(void* const* d_in, const int* in_sizes, int n_in,
                              void* d_out, int out_size)
{
    static const long long EXP[14] = {12800000LL, 1600000LL, 16384LL, 64LL, 1024LL,
                                      16LL, 65536LL, 256LL, 256LL, 256LL,
                                      4096LL, 16LL, 16LL, 16LL};
    const void* slot[14];
    for (int i = 0; i < 14; i++) slot[i] = (n_in > i) ? d_in[i] : d_in[0];

    if (n_in >= 14) {
        bool id = true;
        for (int i = 0; i < 14; i++) {
            long long s = in_sizes[i];
            if (i == 1) { if (s != 1600000LL && s != 3200000LL) id = false; }
            else if (s != EXP[i]) id = false;
        }
        if (!id) {
            bool used[64];
            for (int i = 0; i < 64; i++) used[i] = false;
            bool ok = true;
            const void* tmp[14];
            for (int j = 0; j < 14 && ok; j++) {
                int found = -1;
                for (int i = 0; i < n_in && i < 64; i++) {
                    if (used[i]) continue;
                    long long s = in_sizes[i];
                    bool m = (j == 1) ? (s == 1600000LL || s == 3200000LL)
                                      : (s == EXP[j]);
                    if (m) { found = i; break; }
                }
                if (found < 0) ok = false;
                else { used[found] = true; tmp[j] = d_in[found]; }
            }
            if (ok) for (int j = 0; j < 14; j++) slot[j] = tmp[j];
        }
    }

    const float* x      = (const float*)slot[0];
    const void*  edges  = slot[1];
    const float* W_g1   = (const float*)slot[2];
    const float* b_g1   = (const float*)slot[3];
    const float* W_g2   = (const float*)slot[4];
    const float* b_g2   = (const float*)slot[5];
    const float* W_a1   = (const float*)slot[6];
    const float* as1    = (const float*)slot[7];
    const float* ad1    = (const float*)slot[8];
    const float* b_a1   = (const float*)slot[9];
    const float* W_a2   = (const float*)slot[10];
    const float* as2    = (const float*)slot[11];
    const float* ad2    = (const float*)slot[12];
    const float* b_a2   = (const float*)slot[13];
    float* out = (float*)d_out;
    (void)out_size;

    // device addresses of __device__ globals used as kernel ARGUMENTS
    void *p_Wcat = nullptr, *p_Hcat = nullptr, *p_Agg = nullptr,
         *p_Wcat2 = nullptr, *p_H2 = nullptr;
    cudaGetSymbolAddress(&p_Wcat,  g_Wcat);
    cudaGetSymbolAddress(&p_Hcat,  g_Hcat);
    cudaGetSymbolAddress(&p_Agg,   g_Agg);
    cudaGetSymbolAddress(&p_Wcat2, g_Wcat2);
    cudaGetSymbolAddress(&p_H2,    g_H2);

    const int T = 256;

    // edge dtype detect + convert
    k_detect<<<1, T>>>(edges);
    k_convert<<<cdiv(Ee, T), T>>>(edges);

    // degree / norm
    k_deg_init <<<cdiv(Nn, T), T>>>();
    k_deg_edges<<<cdiv(Ee, T), T>>>();
    k_deg_fin  <<<cdiv(Nn, T), T>>>();

    // packed weights
    k_build_w1<<<cdiv(Fdim * C1, T), T>>>(W_g1, W_a1);
    k_build_w2<<<cdiv(C1 * C2, T), T>>>(W_g2, W_a2);

    // GEMM1: Hcat = x @ Wcat   (50000 x 256 @ 256 x 320)
    {
        dim3 grid(C1 / 64, cdiv(Nn, 128));
        k_sgemm4<128, 64, 32, 8, 8><<<grid, 128>>>(
            x, (const float*)p_Wcat, (float*)p_Hcat, Nn, C1, Fdim);
    }

    // GAT1 softmax pipeline
    k_scores1<<<cdiv(Nn * NHEAD, T), T>>>(as1, ad1);
    k_m1_edges<<<cdiv(Ee, T), T>>>();
    k_d1_init <<<cdiv(Nn * NHEAD, T), T>>>();
    k_d1_edges<<<cdiv(Ee, T), T>>>();

    // layer-1 aggregation + relu/bias
    k_agg1_init <<<cdiv(Nn * (C1 / 4), T), T>>>();
    k_agg1_edges<<<cdiv(Ee * 32, T), T>>>();
    k_relu_bias <<<cdiv(Nn * (C1 / 4), T), T>>>(b_g1, b_a1);

    // GEMM2: H2 = X2 @ Wcat2   (50000 x 320 @ 320 x 32)
    {
        dim3 grid(1, cdiv(Nn, 128));
        k_sgemm4<128, 32, 32, 8, 4><<<grid, 128>>>(
            (const float*)p_Agg, (const float*)p_Wcat2, (float*)p_H2, Nn, C2, C1);
    }

    // GAT2 softmax pipeline
    k_scores2<<<cdiv(Nn, T), T>>>(as2, ad2);
    k_m2_edges<<<cdiv(Ee, T), T>>>();
    k_d2_init <<<cdiv(Nn, T), T>>>();
    k_d2_edges<<<cdiv(Ee, T), T>>>();

    // layer-2 aggregation into d_out
    k_out_init <<<cdiv(Nn * C2, T), T>>>(out, b_g2, b_a2);
    k_out_edges<<<cdiv(Ee * 8, T), T>>>(out);
}

// round 7
// speedup vs baseline: 2.1239x; 1.2795x over previous
#include <cuda_runtime.h>
#include <cstdint>

#define Nn    50000
#define Fdim  256
#define Hdim  64
#define NHEAD 4
#define Ee    800000
#define OUTC  16
#define C1    320   // 64 (GCN1) + 256 (GAT1 = 4 heads * 64)
#define C2    32    // 16 (GCN2) + 16 (GAT2)

// ---------------- scratch (static device globals) ----------------------------
static __device__ int   g_mode;
static __device__ __align__(16) int   g_src[Ee];
static __device__ __align__(16) int   g_dst[Ee];
static __device__ __align__(16) int   g_cnt[Nn];       // in-degree (no self loop)
static __device__ __align__(16) int   g_rowptr[Nn + 1];
static __device__ __align__(16) int   g_off[Nn];       // running fill offsets
static __device__ __align__(16) int   g_csr[Ee];       // src ids grouped by dst
static __device__ __align__(16) float g_dinv[Nn];
static __device__ __align__(16) float g_Wcat[Fdim * C1];
static __device__ __align__(16) float g_Hcat[(size_t)Nn * C1];
static __device__ __align__(16) float g_Agg [(size_t)Nn * C1];
static __device__ __align__(16) float g_ssrc[Nn * NHEAD];
static __device__ __align__(16) float g_sdst[Nn * NHEAD];
static __device__ __align__(16) float g_Wcat2[C1 * C2];
static __device__ __align__(16) float g_H2[(size_t)Nn * C2];
static __device__ __align__(16) float g_s2s[Nn];
static __device__ __align__(16) float g_s2d[Nn];

// ---------------- helpers ----------------------------------------------------
__device__ __forceinline__ float leaky(float x) { return x > 0.f ? x : 0.2f * x; }
__device__ __forceinline__ int clampN(int v) {
    return v < 0 ? 0 : (v >= Nn ? Nn - 1 : v);
}

// ---------------- edge dtype detect + convert --------------------------------
__global__ void k_detect(const void* edges) {
    const unsigned int* p = (const unsigned int*)edges;
    __shared__ int en, on, big;
    if (threadIdx.x == 0) { en = 0; on = 0; big = 0; }
    __syncthreads();
    for (int i = threadIdx.x; i < 1024; i += blockDim.x) {
        unsigned int a = p[2 * i];
        unsigned int b = p[2 * i + 1];
        if (a != 0) en = 1;
        if (b != 0) on = 1;
        if (a >= (1u << 20) || b >= (1u << 20)) big = 1;
    }
    __syncthreads();
    if (threadIdx.x == 0) {
        int mode;
        if (on == 0 && en != 0)      mode = 1;  // int64
        else if (en == 0 && on != 0) mode = 3;  // float64
        else if (big)                mode = 2;  // float32
        else                         mode = 0;  // int32
        g_mode = mode;
    }
}

__global__ void k_convert(const void* edges) {
    int e = blockIdx.x * blockDim.x + threadIdx.x;
    if (e >= Ee) return;
    int s, d;
    int mode = g_mode;
    if (mode == 0) {
        const int* q = (const int*)edges;
        s = q[e]; d = q[Ee + e];
    } else if (mode == 1) {
        const int* q = (const int*)edges;
        s = q[2 * e]; d = q[2 * (Ee + e)];
    } else if (mode == 2) {
        const float* q = (const float*)edges;
        s = (int)q[e]; d = (int)q[Ee + e];
    } else {
        const double* q = (const double*)edges;
        s = (int)q[e]; d = (int)q[Ee + e];
    }
    g_src[e] = clampN(s);
    g_dst[e] = clampN(d);
}

// ---------------- CSR build (counting sort by dst) ---------------------------
__global__ void k_cnt_reset() {
    int i = blockIdx.x * blockDim.x + threadIdx.x;
    if (i < Nn) g_cnt[i] = 0;
}
__global__ void k_count() {
    int e = blockIdx.x * blockDim.x + threadIdx.x;
    if (e < Ee) atomicAdd(&g_cnt[g_dst[e]], 1);
}
// single-block inclusive scan over g_cnt -> g_rowptr / g_off
__global__ void k_scan() {
    __shared__ int sh[1024];
    int tid = threadIdx.x;
    int carry = 0;
    if (tid == 0) g_rowptr[0] = 0;
    for (int base = 0; base < Nn; base += 1024) {
        int i = base + tid;
        int v = (i < Nn) ? g_cnt[i] : 0;
        sh[tid] = v;
        __syncthreads();
        for (int off = 1; off < 1024; off <<= 1) {
            int t = (tid >= off) ? sh[tid - off] : 0;
            __syncthreads();
            sh[tid] += t;
            __syncthreads();
        }
        if (i < Nn) {
            g_rowptr[i + 1] = carry + sh[tid];
            g_off[i]        = carry + sh[tid] - v;
        }
        int last = sh[1023];
        __syncthreads();           // protect sh before next iteration's writes
        carry += last;
    }
}
__global__ void k_fill() {
    int e = blockIdx.x * blockDim.x + threadIdx.x;
    if (e >= Ee) return;
    int d = g_dst[e];
    int pos = atomicAdd(&g_off[d], 1);
    g_csr[pos] = g_src[e];
}
__global__ void k_dinv() {
    int i = blockIdx.x * blockDim.x + threadIdx.x;
    if (i < Nn) g_dinv[i] = rsqrtf((float)(g_cnt[i] + 1));   // +1 self loop
}

// ---------------- weight packing ---------------------------------------------
__global__ void k_build_w1(const float* __restrict__ Wg, const float* __restrict__ Wa) {
    int idx = blockIdx.x * blockDim.x + threadIdx.x;
    if (idx >= Fdim * C1) return;
    int r = idx / C1, c = idx % C1;
    g_Wcat[idx] = (c < Hdim) ? Wg[r * Hdim + c] : Wa[r * 256 + (c - Hdim)];
}
__global__ void k_build_w2(const float* __restrict__ Wg2, const float* __restrict__ Wa2) {
    int idx = blockIdx.x * blockDim.x + threadIdx.x;
    if (idx >= C1 * C2) return;
    int r = idx / C2, c = idx % C2;
    float v = 0.f;
    if (r < Hdim && c < OUTC)          v = Wg2[r * OUTC + c];
    else if (r >= Hdim && c >= OUTC)   v = Wa2[(r - Hdim) * OUTC + (c - OUTC)];
    g_Wcat2[idx] = v;
}

// ---------------- SGEMM, float4-vectorized -----------------------------------
template<int BM, int BN, int BK, int TM, int TN>
__global__ void __launch_bounds__((BM / TM) * (BN / TN))
k_sgemm4(const float* __restrict__ A, const float* __restrict__ B,
         float* __restrict__ C, int M, int N, int K)
{
    constexpr int NT = (BM / TM) * (BN / TN);
    __shared__ float As[BK][BM];
    __shared__ float Bs[BK][BN];
    const int tid = threadIdx.x;
    const int rowBase = blockIdx.y * BM;
    const int colBase = blockIdx.x * BN;
    const int trow = tid / (BN / TN);
    const int tcol = tid % (BN / TN);

    float acc[TM][TN];
#pragma unroll
    for (int i = 0; i < TM; i++)
#pragma unroll
        for (int j = 0; j < TN; j++) acc[i][j] = 0.f;

    for (int k0 = 0; k0 < K; k0 += BK) {
        constexpr int AF = BM * BK / 4;
#pragma unroll
        for (int f = tid; f < AF; f += NT) {
            int m  = f % BM;
            int kk = (f / BM) * 4;
            int gr = rowBase + m;
            float4 v = make_float4(0.f, 0.f, 0.f, 0.f);
            if (gr < M) v = *(const float4*)&A[(size_t)gr * K + k0 + kk];
            As[kk + 0][m] = v.x;
            As[kk + 1][m] = v.y;
            As[kk + 2][m] = v.z;
            As[kk + 3][m] = v.w;
        }
        constexpr int BF = BK * BN / 4;
#pragma unroll
        for (int f = tid; f < BF; f += NT) {
            int k  = f / (BN / 4);
            int nn = (f % (BN / 4)) * 4;
            *(float4*)&Bs[k][nn] = *(const float4*)&B[(size_t)(k0 + k) * N + colBase + nn];
        }
        __syncthreads();
#pragma unroll
        for (int k = 0; k < BK; k++) {
            float ra[TM], rb[TN];
#pragma unroll
            for (int i = 0; i < TM; i += 4)
                *(float4*)&ra[i] = *(const float4*)&As[k][trow * TM + i];
#pragma unroll
            for (int j = 0; j < TN; j += 4)
                *(float4*)&rb[j] = *(const float4*)&Bs[k][tcol * TN + j];
#pragma unroll
            for (int i = 0; i < TM; i++)
#pragma unroll
                for (int j = 0; j < TN; j++) acc[i][j] += ra[i] * rb[j];
        }
        __syncthreads();
    }
#pragma unroll
    for (int i = 0; i < TM; i++) {
        int gr = rowBase + trow * TM + i;
        if (gr >= M) continue;
#pragma unroll
        for (int j = 0; j < TN; j += 4)
            *(float4*)&C[(size_t)gr * N + colBase + tcol * TN + j] = *(float4*)&acc[i][j];
    }
}

// ---------------- GAT1 scores -------------------------------------------------
__global__ void k_scores1(const float* __restrict__ a_s, const float* __restrict__ a_d) {
    int idx = blockIdx.x * blockDim.x + threadIdx.x;
    if (idx >= Nn * NHEAD) return;
    int n = idx / NHEAD, h = idx % NHEAD;
    const float* row = g_Hcat + (size_t)n * C1 + Hdim + h * Hdim;
    float s1 = 0.f, s2 = 0.f;
#pragma unroll 8
    for (int c = 0; c < Hdim; c++) {
        float v = row[c];
        s1 += v * a_s[h * Hdim + c];
        s2 += v * a_d[h * Hdim + c];
    }
    g_ssrc[idx] = s1;
    g_sdst[idx] = s2;
}

// ---------------- fused layer-1: softmax stats + gather agg + bias + relu ----
__global__ void __launch_bounds__(256)
k_fused1(const float* __restrict__ bg, const float* __restrict__ ba) {
    int n    = (blockIdx.x * blockDim.x + threadIdx.x) >> 5;
    int lane = threadIdx.x & 31;
    if (n >= Nn) return;
    const int start = g_rowptr[n], end = g_rowptr[n + 1];

    float4 sd = *(const float4*)&g_sdst[n * 4];
    float4 ss = *(const float4*)&g_ssrc[n * 4];
    float selfe_x = leaky(ss.x + sd.x), selfe_y = leaky(ss.y + sd.y);
    float selfe_z = leaky(ss.z + sd.z), selfe_w = leaky(ss.w + sd.w);

    // ---- segment max over in-neighbors (+self) ----
    float4 mx = make_float4(selfe_x, selfe_y, selfe_z, selfe_w);
    for (int j = start + lane; j < end; j += 32) {
        int u = g_csr[j];
        float4 su = *(const float4*)&g_ssrc[u * 4];
        mx.x = fmaxf(mx.x, leaky(su.x + sd.x));
        mx.y = fmaxf(mx.y, leaky(su.y + sd.y));
        mx.z = fmaxf(mx.z, leaky(su.z + sd.z));
        mx.w = fmaxf(mx.w, leaky(su.w + sd.w));
    }
#pragma unroll
    for (int o = 16; o; o >>= 1) {
        mx.x = fmaxf(mx.x, __shfl_xor_sync(~0u, mx.x, o));
        mx.y = fmaxf(mx.y, __shfl_xor_sync(~0u, mx.y, o));
        mx.z = fmaxf(mx.z, __shfl_xor_sync(~0u, mx.z, o));
        mx.w = fmaxf(mx.w, __shfl_xor_sync(~0u, mx.w, o));
    }

    // ---- denom ----
    float4 den = make_float4(0.f, 0.f, 0.f, 0.f);
    if (lane == 0) {
        den.x = expf(selfe_x - mx.x); den.y = expf(selfe_y - mx.y);
        den.z = expf(selfe_z - mx.z); den.w = expf(selfe_w - mx.w);
    }
    for (int j = start + lane; j < end; j += 32) {
        int u = g_csr[j];
        float4 su = *(const float4*)&g_ssrc[u * 4];
        den.x += expf(leaky(su.x + sd.x) - mx.x);
        den.y += expf(leaky(su.y + sd.y) - mx.y);
        den.z += expf(leaky(su.z + sd.z) - mx.z);
        den.w += expf(leaky(su.w + sd.w) - mx.w);
    }
#pragma unroll
    for (int o = 16; o; o >>= 1) {
        den.x += __shfl_xor_sync(~0u, den.x, o);
        den.y += __shfl_xor_sync(~0u, den.y, o);
        den.z += __shfl_xor_sync(~0u, den.z, o);
        den.w += __shfl_xor_sync(~0u, den.w, o);
    }
    float4 rd = make_float4(1.f / den.x, 1.f / den.y, 1.f / den.z, 1.f / den.w);

    // ---- accumulate: self contribution ----
    const float di = g_dinv[n];
    float a_self[NHEAD] = {expf(selfe_x - mx.x) * rd.x, expf(selfe_y - mx.y) * rd.y,
                           expf(selfe_z - mx.z) * rd.z, expf(selfe_w - mx.w) * rd.w};
    float wg_self = di * di;
    float acc[10];
    const float* hn = g_Hcat + (size_t)n * C1;
#pragma unroll
    for (int k = 0; k < 10; k++) {
        int c = lane + 32 * k;
        float s = (c < Hdim) ? wg_self : a_self[(c - Hdim) >> 6];
        acc[k] = s * hn[c];
    }

    // ---- neighbors, chunked by 32 with shfl broadcast ----
    for (int base = start; base < end; base += 32) {
        int j = base + lane;
        int   u_l = 0;
        float wg_l = 0.f, ax_l = 0.f, ay_l = 0.f, az_l = 0.f, aw_l = 0.f;
        if (j < end) {
            u_l = g_csr[j];
            wg_l = g_dinv[u_l] * di;
            float4 su = *(const float4*)&g_ssrc[u_l * 4];
            ax_l = expf(leaky(su.x + sd.x) - mx.x) * rd.x;
            ay_l = expf(leaky(su.y + sd.y) - mx.y) * rd.y;
            az_l = expf(leaky(su.z + sd.z) - mx.z) * rd.z;
            aw_l = expf(leaky(su.w + sd.w) - mx.w) * rd.w;
        }
        int cnt = min(32, end - base);
        for (int t = 0; t < cnt; t++) {
            int   u  = __shfl_sync(~0u, u_l,  t);
            float wg = __shfl_sync(~0u, wg_l, t);
            float ax = __shfl_sync(~0u, ax_l, t);
            float ay = __shfl_sync(~0u, ay_l, t);
            float az = __shfl_sync(~0u, az_l, t);
            float aw = __shfl_sync(~0u, aw_l, t);
            const float* hu = g_Hcat + (size_t)u * C1;
#pragma unroll
            for (int k = 0; k < 10; k++) {
                int c = lane + 32 * k;
                float s = (c < 64) ? wg : (c < 128) ? ax : (c < 192) ? ay
                                        : (c < 256) ? az : aw;
                acc[k] += s * hu[c];
            }
        }
    }

    // ---- bias + relu + store ----
    float* an = g_Agg + (size_t)n * C1;
#pragma unroll
    for (int k = 0; k < 10; k++) {
        int c = lane + 32 * k;
        float b = (c < Hdim) ? bg[c] : ba[c - Hdim];
        an[c] = fmaxf(acc[k] + b, 0.f);
    }
}

// ---------------- GAT2 scores -------------------------------------------------
__global__ void k_scores2(const float* __restrict__ a_s, const float* __restrict__ a_d) {
    int n = blockIdx.x * blockDim.x + threadIdx.x;
    if (n >= Nn) return;
    const float* row = g_H2 + (size_t)n * C2 + OUTC;
    float s1 = 0.f, s2 = 0.f;
#pragma unroll
    for (int c = 0; c < OUTC; c++) {
        float v = row[c];
        s1 += v * a_s[c];
        s2 += v * a_d[c];
    }
    g_s2s[n] = s1;
    g_s2d[n] = s2;
}

// ---------------- fused layer-2: stats + gather + bias -> d_out ---------------
__global__ void __launch_bounds__(256)
k_fused2(float* __restrict__ out,
         const float* __restrict__ bg2, const float* __restrict__ ba2) {
    int n    = (blockIdx.x * blockDim.x + threadIdx.x) >> 5;
    int lane = threadIdx.x & 31;
    if (n >= Nn) return;
    const int start = g_rowptr[n], end = g_rowptr[n + 1];

    const float sdn = g_s2d[n];
    const float selfe = leaky(g_s2s[n] + sdn);

    float mx = selfe;
    for (int j = start + lane; j < end; j += 32)
        mx = fmaxf(mx, leaky(g_s2s[g_csr[j]] + sdn));
#pragma unroll
    for (int o = 16; o; o >>= 1) mx = fmaxf(mx, __shfl_xor_sync(~0u, mx, o));

    float den = (lane == 0) ? expf(selfe - mx) : 0.f;
    for (int j = start + lane; j < end; j += 32)
        den += expf(leaky(g_s2s[g_csr[j]] + sdn) - mx);
#pragma unroll
    for (int o = 16; o; o >>= 1) den += __shfl_xor_sync(~0u, den, o);
    float rd = 1.f / den;

    const float di = g_dinv[n];
    float s_self = (lane < OUTC) ? di * di : expf(selfe - mx) * rd;
    float acc = s_self * g_H2[(size_t)n * C2 + lane];

    for (int base = start; base < end; base += 32) {
        int j = base + lane;
        int   u_l = 0;
        float wg_l = 0.f, a_l = 0.f;
        if (j < end) {
            u_l = g_csr[j];
            wg_l = g_dinv[u_l] * di;
            a_l  = expf(leaky(g_s2s[u_l] + sdn) - mx) * rd;
        }
        int cnt = min(32, end - base);
        for (int t = 0; t < cnt; t++) {
            int   u  = __shfl_sync(~0u, u_l,  t);
            float wg = __shfl_sync(~0u, wg_l, t);
            float a  = __shfl_sync(~0u, a_l,  t);
            float s  = (lane < OUTC) ? wg : a;
            acc += s * g_H2[(size_t)u * C2 + lane];
        }
    }

    float b = (lane < OUTC) ? bg2[lane] : ba2[lane - OUTC];
    out[(size_t)n * C2 + lane] = acc + b;
}

// ---------------- launch ------------------------------------------------------
static inline int cdiv(int a, int b) { return (a + b - 1) / b; }

extern "C" void kernel_launch(void* const* d_in, const int* in_sizes, int n_in,
                              void* d_out, int out_size)
{
    static const long long EXP[14] = {12800000LL, 1600000LL, 16384LL, 64LL, 1024LL,
                                      16LL, 65536LL, 256LL, 256LL, 256LL,
                                      4096LL, 16LL, 16LL, 16LL};
    const void* slot[14];
    for (int i = 0; i < 14; i++) slot[i] = (n_in > i) ? d_in[i] : d_in[0];

    if (n_in >= 14) {
        bool id = true;
        for (int i = 0; i < 14; i++) {
            long long s = in_sizes[i];
            if (i == 1) { if (s != 1600000LL && s != 3200000LL) id = false; }
            else if (s != EXP[i]) id = false;
        }
        if (!id) {
            bool used[64];
            for (int i = 0; i < 64; i++) used[i] = false;
            bool ok = true;
            const void* tmp[14];
            for (int j = 0; j < 14 && ok; j++) {
                int found = -1;
                for (int i = 0; i < n_in && i < 64; i++) {
                    if (used[i]) continue;
                    long long s = in_sizes[i];
                    bool m = (j == 1) ? (s == 1600000LL || s == 3200000LL)
                                      : (s == EXP[j]);
                    if (m) { found = i; break; }
                }
                if (found < 0) ok = false;
                else { used[found] = true; tmp[j] = d_in[found]; }
            }
            if (ok) for (int j = 0; j < 14; j++) slot[j] = tmp[j];
        }
    }

    const float* x      = (const float*)slot[0];
    const void*  edges  = slot[1];
    const float* W_g1   = (const float*)slot[2];
    const float* b_g1   = (const float*)slot[3];
    const float* W_g2   = (const float*)slot[4];
    const float* b_g2   = (const float*)slot[5];
    const float* W_a1   = (const float*)slot[6];
    const float* as1    = (const float*)slot[7];
    const float* ad1    = (const float*)slot[8];
    const float* b_a1   = (const float*)slot[9];
    const float* W_a2   = (const float*)slot[10];
    const float* as2    = (const float*)slot[11];
    const float* ad2    = (const float*)slot[12];
    const float* b_a2   = (const float*)slot[13];
    float* out = (float*)d_out;
    (void)out_size;

    void *p_Wcat = nullptr, *p_Hcat = nullptr, *p_Agg = nullptr,
         *p_Wcat2 = nullptr, *p_H2 = nullptr;
    cudaGetSymbolAddress(&p_Wcat,  g_Wcat);
    cudaGetSymbolAddress(&p_Hcat,  g_Hcat);
    cudaGetSymbolAddress(&p_Agg,   g_Agg);
    cudaGetSymbolAddress(&p_Wcat2, g_Wcat2);
    cudaGetSymbolAddress(&p_H2,    g_H2);

    const int T = 256;

    // edges: dtype detect + convert, then CSR build
    k_detect<<<1, T>>>(edges);
    k_convert<<<cdiv(Ee, T), T>>>(edges);
    k_cnt_reset<<<cdiv(Nn, T), T>>>();
    k_count<<<cdiv(Ee, T), T>>>();
    k_scan<<<1, 1024>>>();
    k_fill<<<cdiv(Ee, T), T>>>();
    k_dinv<<<cdiv(Nn, T), T>>>();

    // packed weights
    k_build_w1<<<cdiv(Fdim * C1, T), T>>>(W_g1, W_a1);
    k_build_w2<<<cdiv(C1 * C2, T), T>>>(W_g2, W_a2);

    // GEMM1: Hcat = x @ Wcat   (50000 x 256 @ 256 x 320)
    {
        dim3 grid(C1 / 64, cdiv(Nn, 128));
        k_sgemm4<128, 64, 32, 8, 8><<<grid, 128>>>(
            x, (const float*)p_Wcat, (float*)p_Hcat, Nn, C1, Fdim);
    }

    // layer-1: scores + fused softmax/aggregation/bias/relu
    k_scores1<<<cdiv(Nn * NHEAD, T), T>>>(as1, ad1);
    k_fused1<<<cdiv(Nn * 32, T), T>>>(b_g1, b_a1);

    // GEMM2: H2 = Agg @ Wcat2   (50000 x 320 @ 320 x 32)
    {
        dim3 grid(1, cdiv(Nn, 128));
        k_sgemm4<128, 32, 32, 8, 4><<<grid, 128>>>(
            (const float*)p_Agg, (const float*)p_Wcat2, (float*)p_H2, Nn, C2, C1);
    }

    // layer-2: scores + fused softmax/aggregation/bias -> out
    k_scores2<<<cdiv(Nn, T), T>>>(as2, ad2);
    k_fused2<<<cdiv(Nn * 32, T), T>>>(out, b_g2, b_a2);
}